// round 1
// baseline (speedup 1.0000x reference)
#include <cuda_runtime.h>
#include <math.h>

#define HW 16384
#define IMW 128

// ---------------- scratch (single static device buffer, no allocations) -------------
// offsets in floats
#define OFF_XS   0ULL                          // [2,192,HW]  LN-scaled (reused for LN2)
#define OFF_T1   3145728ULL                    // [2,192,HW]  q pre-dw / attn out
#define OFF_Q    6291456ULL                    // [2,192,HW]  q after dw
#define OFF_KVP  9437184ULL                    // [2,384,HW]  kv pre-dw / gelu-gate out
#define OFF_KV   22020096ULL                   // [2,384,HW]  kv after dw
#define OFF_YP   34603008ULL                   // [2,768,HW]  pin out pre-dw
#define OFF_Y    59768832ULL                   // [2,768,HW]  y after dw
#define OFF_M1   84934656ULL                   // [2,192]
#define OFF_MF   (OFF_M1 + 384ULL)             // [2,192]
#define OFF_RQ   (OFF_MF + 384ULL)             // [2,192]
#define OFF_RK   (OFF_RQ + 384ULL)             // [2,192]
#define OFF_SP   (OFF_RK + 384ULL)             // [2,6,8,32,32]
#define OFF_ATT  (OFF_SP + 98304ULL)           // [2,6,32,32]
#define SCRATCH_TOTAL (OFF_ATT + 12288ULL)

__device__ float g_scratch[SCRATCH_TOTAL];

// ---------------- tiny prep: per-batch channel multipliers + k_v passthrough --------
__global__ void prep_kernel(const float* __restrict__ kv,
                            const float* __restrict__ wkR,   // [144,192]
                            const float* __restrict__ wkI,   // [48,64]
                            const float* __restrict__ wffk,  // [192,256]
                            float* __restrict__ m1, float* __restrict__ mf,
                            float* __restrict__ out_tail, int tail) {
    int t = blockIdx.x * blockDim.x + threadIdx.x;
    if (t < 384) {                       // m1: (kvr|kvi) + 1, per (b,c)
        int b = t / 192, c = t % 192;
        float acc = 1.0f;
        if (c < 144) {
            const float* w = wkR + c * 192;
            const float* v = kv + b * 256;
            for (int i = 0; i < 192; i++) acc += w[i] * v[i];
        } else {
            const float* w = wkI + (c - 144) * 64;
            const float* v = kv + b * 256 + 192;
            for (int i = 0; i < 64; i++) acc += w[i] * v[i];
        }
        m1[t] = acc;
    } else if (t < 768) {                // mf: kvf + 1
        int u = t - 384;
        int b = u / 192, c = u % 192;
        float acc = 1.0f;
        const float* w = wffk + c * 256;
        const float* v = kv + b * 256;
        for (int i = 0; i < 256; i++) acc += w[i] * v[i];
        mf[u] = acc;
    } else if (t - 768 < tail) {         // copy k_v to output tail
        out_tail[t - 768] = kv[t - 768];
    }
}

// ---------------- channel LayerNorm (over 192 ch) * per-(b,c) multiplier ------------
__global__ void ln_scale_kernel(const float* __restrict__ x,
                                const float* __restrict__ w, const float* __restrict__ bias,
                                const float* __restrict__ m, float* __restrict__ out) {
    int p = blockIdx.x * blockDim.x + threadIdx.x;   // 0..32767  (b*HW + pixel)
    int b  = p >> 14;
    int px = p & (HW - 1);
    const float* xb = x + (size_t)b * 192 * HW + px;
    float s = 0.f, s2 = 0.f;
    #pragma unroll 8
    for (int c = 0; c < 192; c++) { float v = xb[(size_t)c * HW]; s += v; s2 += v * v; }
    float mu   = s * (1.0f / 192.0f);
    float var  = s2 * (1.0f / 192.0f) - mu * mu;
    float rstd = rsqrtf(var + 1e-5f);
    float* ob = out + (size_t)b * 192 * HW + px;
    const float* mb = m + b * 192;
    #pragma unroll 8
    for (int c = 0; c < 192; c++) {
        float v = (xb[(size_t)c * HW] - mu) * rstd * w[c] + bias[c];
        ob[(size_t)c * HW] = v * mb[c];
    }
}

// ---------------- generic 1x1 conv GEMM: out[b,oc,p] = W[oc,ic] @ in[b,icoff+ic,p] ---
// block: 64 output channels x 128 pixels; thread: 8 oc x 4 px; optional residual add
__global__ void conv1x1_kernel(const float* __restrict__ in, int ictot, int icoff, int ic,
                               const float* __restrict__ Wt, int octot,
                               const float* __restrict__ res, float* __restrict__ out) {
    __shared__ float sIn[16 * 128];
    __shared__ float sW[64 * 16];
    int b      = blockIdx.z;
    int ocbase = blockIdx.y * 64;
    int pbase  = blockIdx.x * 128;
    int t  = threadIdx.x;        // 256
    int tx = t & 31;             // pixel group (4 px each)
    int ty = t >> 5;             // oc group (8 oc each)

    float acc[8][4];
    #pragma unroll
    for (int i = 0; i < 8; i++)
        #pragma unroll
        for (int j = 0; j < 4; j++) acc[i][j] = 0.f;

    const float* inb = in + ((size_t)b * ictot + icoff) * HW + pbase;

    for (int k0 = 0; k0 < ic; k0 += 16) {
        #pragma unroll
        for (int l = 0; l < 8; l++) {              // 16x128 input tile
            int idx = t + l * 256;
            int r = idx >> 7, col = idx & 127;
            sIn[idx] = inb[(size_t)(k0 + r) * HW + col];
        }
        #pragma unroll
        for (int l = 0; l < 4; l++) {              // 64x16 weight tile
            int idx = t * 4 + l;
            int r = idx >> 4, cc = idx & 15;
            sW[idx] = Wt[(size_t)(ocbase + r) * ic + k0 + cc];
        }
        __syncthreads();
        #pragma unroll
        for (int kk = 0; kk < 16; kk++) {
            float4 a = reinterpret_cast<const float4*>(sIn + kk * 128)[tx];
            float av[4] = {a.x, a.y, a.z, a.w};
            #pragma unroll
            for (int i = 0; i < 8; i++) {
                float wv = sW[(ty * 8 + i) * 16 + kk];
                #pragma unroll
                for (int j = 0; j < 4; j++) acc[i][j] += wv * av[j];
            }
        }
        __syncthreads();
    }

    #pragma unroll
    for (int i = 0; i < 8; i++) {
        int oc = ocbase + ty * 8 + i;
        size_t off = ((size_t)b * octot + oc) * HW + pbase + tx * 4;
        float4 r4;
        if (res) {
            r4 = reinterpret_cast<const float4*>(res + off)[0];
            r4.x += acc[i][0]; r4.y += acc[i][1]; r4.z += acc[i][2]; r4.w += acc[i][3];
        } else {
            r4 = make_float4(acc[i][0], acc[i][1], acc[i][2], acc[i][3]);
        }
        reinterpret_cast<float4*>(out + off)[0] = r4;
    }
}

// ---------------- depthwise 3x3, zero pad ------------------------------------------
__global__ void dwconv_kernel(const float* __restrict__ in, const float* __restrict__ w,
                              int C, float* __restrict__ out) {
    size_t idx = (size_t)blockIdx.x * blockDim.x + threadIdx.x;
    size_t total = (size_t)2 * C * HW;
    if (idx >= total) return;
    int x = (int)(idx & 127);
    int y = (int)((idx >> 7) & 127);
    int c = (int)((idx >> 14) % C);
    const float* wp = w + c * 9;
    const float* ip = in + (idx - (idx & (HW - 1)));   // plane base
    float acc = 0.f;
    #pragma unroll
    for (int ky = 0; ky < 3; ky++) {
        int yy = y + ky - 1;
        if (yy < 0 || yy > 127) continue;
        #pragma unroll
        for (int kx = 0; kx < 3; kx++) {
            int xx = x + kx - 1;
            if (xx < 0 || xx > 127) continue;
            acc += ip[yy * IMW + xx] * wp[ky * 3 + kx];
        }
    }
    out[idx] = acc;
}

// ---------------- reciprocal L2 norm over HW per (b, channel) row ------------------
__global__ void rnorm_kernel(const float* __restrict__ t, int chtot, int coff,
                             float* __restrict__ rn) {
    int row = blockIdx.x;                 // 0..383  (b*192 + c)
    int b = row / 192, c = row % 192;
    const float* p = t + ((size_t)b * chtot + coff + c) * HW;
    float s = 0.f;
    for (int i = threadIdx.x; i < HW; i += blockDim.x) { float v = p[i]; s += v * v; }
    __shared__ float red[8];
    #pragma unroll
    for (int o = 16; o; o >>= 1) s += __shfl_down_sync(0xffffffffu, s, o);
    if ((threadIdx.x & 31) == 0) red[threadIdx.x >> 5] = s;
    __syncthreads();
    if (threadIdx.x < 32) {
        s = (threadIdx.x < 8) ? red[threadIdx.x] : 0.f;
        #pragma unroll
        for (int o = 4; o; o >>= 1) s += __shfl_down_sync(0xffffffffu, s, o);
        if (threadIdx.x == 0) rn[row] = 1.0f / fmaxf(sqrtf(s), 1e-12f);
    }
}

// ---------------- q@k^T partials: S[b,h,pc,32,32] over 2048-pixel chunks -----------
__global__ void qk_kernel(const float* __restrict__ q, const float* __restrict__ kv,
                          float* __restrict__ Sp) {
    int pc = blockIdx.x, hh = blockIdx.y, b = blockIdx.z;
    const float* qb = q  + ((size_t)b * 192 + hh * 32) * HW + pc * 2048;
    const float* kb = kv + ((size_t)b * 384 + hh * 32) * HW + pc * 2048;
    __shared__ float sq[32 * 33];
    __shared__ float sk[32 * 33];
    int t = threadIdx.x;       // 256
    int i = t & 31, jg = t >> 5;
    float acc[4] = {0.f, 0.f, 0.f, 0.f};
    for (int p0 = 0; p0 < 2048; p0 += 32) {
        #pragma unroll
        for (int l = 0; l < 4; l++) {
            int idx = t + l * 256;
            int r = idx >> 5, cc = idx & 31;
            sq[r * 33 + cc] = qb[(size_t)r * HW + p0 + cc];
            sk[r * 33 + cc] = kb[(size_t)r * HW + p0 + cc];
        }
        __syncthreads();
        #pragma unroll
        for (int p = 0; p < 32; p++) {
            float a = sq[i * 33 + p];
            #pragma unroll
            for (int j = 0; j < 4; j++) acc[j] += a * sk[(jg * 4 + j) * 33 + p];
        }
        __syncthreads();
    }
    float* sp = Sp + (((size_t)(b * 6 + hh) * 8 + pc) * 1024);
    #pragma unroll
    for (int j = 0; j < 4; j++) sp[i * 32 + jg * 4 + j] = acc[j];
}

// ---------------- reduce partials, apply norms+temp, softmax over last dim ---------
__global__ void softmax_kernel(const float* __restrict__ Sp, const float* __restrict__ rq,
                               const float* __restrict__ rk, const float* __restrict__ temp,
                               float* __restrict__ attn) {
    int bh = blockIdx.x;                 // 0..11
    int b = bh / 6, hh = bh % 6;
    int t = threadIdx.x;                 // 1024
    int i = t >> 5, j = t & 31;
    const float* sp = Sp + (size_t)bh * 8192 + i * 32 + j;
    float s = 0.f;
    #pragma unroll
    for (int pc = 0; pc < 8; pc++) s += sp[pc * 1024];
    s *= rq[b * 192 + hh * 32 + i] * rk[b * 192 + hh * 32 + j] * temp[hh];
    float mx = s;
    #pragma unroll
    for (int o = 16; o; o >>= 1) mx = fmaxf(mx, __shfl_xor_sync(0xffffffffu, mx, o));
    float e = expf(s - mx);
    float sum = e;
    #pragma unroll
    for (int o = 16; o; o >>= 1) sum += __shfl_xor_sync(0xffffffffu, sum, o);
    attn[(size_t)bh * 1024 + i * 32 + j] = e / sum;
}

// ---------------- out = attn @ v ----------------------------------------------------
__global__ void av_kernel(const float* __restrict__ attn, const float* __restrict__ kv,
                          float* __restrict__ out) {
    int b = blockIdx.z, hh = blockIdx.y;
    int p = blockIdx.x * 256 + threadIdx.x;
    __shared__ float sA[1024];
    for (int l = threadIdx.x; l < 1024; l += 256)
        sA[l] = attn[(size_t)(b * 6 + hh) * 1024 + l];
    __syncthreads();
    const float* vb = kv + ((size_t)b * 384 + 192 + hh * 32) * HW + p;
    float v[32];
    #pragma unroll
    for (int e = 0; e < 32; e++) v[e] = vb[(size_t)e * HW];
    float* ob = out + ((size_t)b * 192 + hh * 32) * HW + p;
    #pragma unroll
    for (int i = 0; i < 32; i++) {
        float acc = 0.f;
        #pragma unroll
        for (int e = 0; e < 32; e++) acc += sA[i * 32 + e] * v[e];
        ob[(size_t)i * HW] = acc;
    }
}

// ---------------- gelu(y1) * y2 -----------------------------------------------------
__global__ void gelu_gate_kernel(const float* __restrict__ y, float* __restrict__ g) {
    size_t idx = (size_t)blockIdx.x * blockDim.x + threadIdx.x;
    if (idx >= (size_t)2 * 384 * HW) return;
    size_t b = idx / ((size_t)384 * HW);
    size_t r = idx % ((size_t)384 * HW);
    const float* yb = y + b * 768 * HW;
    float a  = yb[r];
    float g2 = yb[r + (size_t)384 * HW];
    float ge = 0.5f * a * (1.0f + erff(a * 0.70710678118654752f));
    g[idx] = ge * g2;
}

// ====================================================================================
extern "C" void kernel_launch(void* const* d_in, const int* in_sizes, int n_in,
                              void* d_out, int out_size) {
    const float* x      = (const float*)d_in[0];
    const float* k_v    = (const float*)d_in[1];
    const float* ln1_w  = (const float*)d_in[2];
    const float* ln1_b  = (const float*)d_in[3];
    const float* temp   = (const float*)d_in[4];
    const float* w_kR   = (const float*)d_in[5];
    const float* w_kI   = (const float*)d_in[6];
    const float* w_qR   = (const float*)d_in[7];
    const float* w_qdw  = (const float*)d_in[8];
    const float* w_kvI  = (const float*)d_in[9];
    const float* w_kvdw = (const float*)d_in[10];
    const float* w_po   = (const float*)d_in[11];
    const float* ln2_w  = (const float*)d_in[12];
    const float* ln2_b  = (const float*)d_in[13];
    const float* w_ffk  = (const float*)d_in[14];
    const float* w_pin  = (const float*)d_in[15];
    const float* w_dw   = (const float*)d_in[16];
    const float* w_pout = (const float*)d_in[17];
    float* out = (float*)d_out;

    float* scratch = nullptr;
    cudaGetSymbolAddress((void**)&scratch, g_scratch);
    float* xs  = scratch + OFF_XS;
    float* t1  = scratch + OFF_T1;
    float* q   = scratch + OFF_Q;
    float* kvp = scratch + OFF_KVP;
    float* kvb = scratch + OFF_KV;
    float* yp  = scratch + OFF_YP;
    float* yb  = scratch + OFF_Y;
    float* m1  = scratch + OFF_M1;
    float* mf  = scratch + OFF_MF;
    float* rq  = scratch + OFF_RQ;
    float* rk  = scratch + OFF_RK;
    float* Sp  = scratch + OFF_SP;
    float* att = scratch + OFF_ATT;

    int tail = out_size - 6291456;
    if (tail < 0) tail = 0;
    if (tail > 512) tail = 512;

    // prep multipliers + k_v passthrough
    prep_kernel<<<5, 256>>>(k_v, w_kR, w_kI, w_ffk, m1, mf, out + 6291456, tail);

    // ---- attention branch ----
    ln_scale_kernel<<<128, 256>>>(x, ln1_w, ln1_b, m1, xs);
    conv1x1_kernel<<<dim3(128, 3, 2), 256>>>(xs, 192, 0, 144, w_qR, 192, nullptr, t1);
    conv1x1_kernel<<<dim3(128, 6, 2), 256>>>(xs, 192, 144, 48, w_kvI, 384, nullptr, kvp);
    dwconv_kernel<<<(2 * 192 * HW) / 256, 256>>>(t1, w_qdw, 192, q);
    dwconv_kernel<<<(2 * 384 * HW) / 256, 256>>>(kvp, w_kvdw, 384, kvb);
    rnorm_kernel<<<384, 256>>>(q, 192, 0, rq);
    rnorm_kernel<<<384, 256>>>(kvb, 384, 0, rk);
    qk_kernel<<<dim3(8, 6, 2), 256>>>(q, kvb, Sp);
    softmax_kernel<<<12, 1024>>>(Sp, rq, rk, temp, att);
    av_kernel<<<dim3(64, 6, 2), 256>>>(att, kvb, t1);
    // x1 = x + conv1x1(attn_out, w_po)  -> written straight into d_out
    conv1x1_kernel<<<dim3(128, 3, 2), 256>>>(t1, 192, 0, 192, w_po, 192, x, out);

    // ---- GDFN feed-forward ----
    ln_scale_kernel<<<128, 256>>>(out, ln2_w, ln2_b, mf, xs);
    conv1x1_kernel<<<dim3(128, 12, 2), 256>>>(xs, 192, 0, 192, w_pin, 768, nullptr, yp);
    dwconv_kernel<<<(2 * 768 * HW) / 256, 256>>>(yp, w_dw, 768, yb);
    gelu_gate_kernel<<<(2 * 384 * HW) / 256, 256>>>(yb, kvp);
    // x_out = x1 + conv1x1(g, w_pout)
    conv1x1_kernel<<<dim3(128, 3, 2), 256>>>(kvp, 384, 0, 384, w_pout, 192, out, out);
}

// round 2
// speedup vs baseline: 1.0677x; 1.0677x over previous
#include <cuda_runtime.h>
#include <math.h>

#define HW 16384
#define IMW 128

// ---------------- scratch (single static device buffer, no allocations) -------------
#define OFF_XS   0ULL                          // [2,192,HW]
#define OFF_T1   3145728ULL                    // [2,192,HW]
#define OFF_Q    6291456ULL                    // [2,192,HW]
#define OFF_KVP  9437184ULL                    // [2,384,HW]
#define OFF_KV   22020096ULL                   // [2,384,HW]
#define OFF_YP   34603008ULL                   // [2,768,HW]
#define OFF_Y    59768832ULL                   // [2,768,HW]
#define OFF_M1   84934656ULL                   // [2,192]
#define OFF_MF   (OFF_M1 + 384ULL)
#define OFF_RQ   (OFF_MF + 384ULL)
#define OFF_RK   (OFF_RQ + 384ULL)
#define OFF_SP   (OFF_RK + 384ULL)             // [2,6,8,32,32]
#define OFF_ATT  (OFF_SP + 98304ULL)           // [2,6,32,32]
// tf32 transposed weights [ic][oc]
#define OFF_WQR  (OFF_ATT + 12288ULL)          // 144*192
#define OFF_WKVI (OFF_WQR + 27648ULL)          // 48*384
#define OFF_WPO  (OFF_WKVI + 18432ULL)         // 192*192
#define OFF_WPIN (OFF_WPO + 36864ULL)          // 192*768
#define OFF_WPOUT (OFF_WPIN + 147456ULL)       // 384*192
#define SCRATCH_TOTAL (OFF_WPOUT + 73728ULL)

__device__ float g_scratch[SCRATCH_TOTAL];

__device__ __forceinline__ unsigned tf32_rna(float f) {
    unsigned r; asm("cvt.rna.tf32.f32 %0, %1;" : "=r"(r) : "f"(f)); return r;
}

__device__ __forceinline__ void mma_tf32(float* d, const unsigned* a, unsigned b0, unsigned b1) {
    asm("mma.sync.aligned.m16n8k8.row.col.f32.tf32.tf32.f32 "
        "{%0,%1,%2,%3},{%4,%5,%6,%7},{%8,%9},{%0,%1,%2,%3};"
        : "+f"(d[0]), "+f"(d[1]), "+f"(d[2]), "+f"(d[3])
        : "r"(a[0]), "r"(a[1]), "r"(a[2]), "r"(a[3]), "r"(b0), "r"(b1));
}

// ---------------- prep: per-batch channel multipliers + k_v passthrough -------------
__global__ void prep_kernel(const float* __restrict__ kv,
                            const float* __restrict__ wkR,
                            const float* __restrict__ wkI,
                            const float* __restrict__ wffk,
                            float* __restrict__ m1, float* __restrict__ mf,
                            float* __restrict__ out_tail, int tail) {
    int t = blockIdx.x * blockDim.x + threadIdx.x;
    if (t < 384) {
        int b = t / 192, c = t % 192;
        float acc = 1.0f;
        if (c < 144) {
            const float* w = wkR + c * 192;
            const float* v = kv + b * 256;
            for (int i = 0; i < 192; i++) acc += w[i] * v[i];
        } else {
            const float* w = wkI + (c - 144) * 64;
            const float* v = kv + b * 256 + 192;
            for (int i = 0; i < 64; i++) acc += w[i] * v[i];
        }
        m1[t] = acc;
    } else if (t < 768) {
        int u = t - 384;
        int b = u / 192, c = u % 192;
        float acc = 1.0f;
        const float* w = wffk + c * 256;
        const float* v = kv + b * 256;
        for (int i = 0; i < 256; i++) acc += w[i] * v[i];
        mf[u] = acc;
    } else if (t - 768 < tail) {
        out_tail[t - 768] = kv[t - 768];
    }
}

// ---------------- weight transpose + tf32 round: W[oc][ic] -> Wt[ic][oc] ------------
__global__ void wprep_kernel(const float* __restrict__ w, int oc, int ic,
                             unsigned* __restrict__ wt) {
    int idx = blockIdx.x * blockDim.x + threadIdx.x;
    if (idx >= oc * ic) return;
    int o = idx / ic, i = idx % ic;
    wt[i * oc + o] = tf32_rna(w[idx]);
}

// ---------------- channel LayerNorm (over 192 ch) * per-(b,c) multiplier ------------
__global__ void ln_scale_kernel(const float* __restrict__ x,
                                const float* __restrict__ w, const float* __restrict__ bias,
                                const float* __restrict__ m, float* __restrict__ out) {
    int p = blockIdx.x * blockDim.x + threadIdx.x;
    int b  = p >> 14;
    int px = p & (HW - 1);
    const float* xb = x + (size_t)b * 192 * HW + px;
    float s = 0.f, s2 = 0.f;
    #pragma unroll 8
    for (int c = 0; c < 192; c++) { float v = xb[(size_t)c * HW]; s += v; s2 += v * v; }
    float mu   = s * (1.0f / 192.0f);
    float var  = s2 * (1.0f / 192.0f) - mu * mu;
    float rstd = rsqrtf(var + 1e-5f);
    float* ob = out + (size_t)b * 192 * HW + px;
    const float* mb = m + b * 192;
    #pragma unroll 8
    for (int c = 0; c < 192; c++) {
        float v = (xb[(size_t)c * HW] - mu) * rstd * w[c] + bias[c];
        ob[(size_t)c * HW] = v * mb[c];
    }
}

// ---------------- tensor-core 1x1 conv: out[b,oc,p] = Wt[ic][oc]^T @ in[b,icoff+ic,p]
// block: 64 oc x 256 px, 8 warps (2 oc x 4 px), warp m32 x n64, tf32 mma m16n8k8
__global__ void conv1x1_tc_kernel(const float* __restrict__ in, int ictot, int icoff, int ic,
                                  const unsigned* __restrict__ Wt, int octot,
                                  const float* __restrict__ res, float* __restrict__ out) {
    __shared__ unsigned sIn[16 * 264];   // [k][px], stride 264 (==8 mod 32)
    __shared__ unsigned sW[16 * 72];     // [k][oc], stride 72  (==8 mod 32)
    int b      = blockIdx.z;
    int ocbase = blockIdx.y * 64;
    int pbase  = blockIdx.x * 256;
    int t    = threadIdx.x;          // 256
    int wid  = t >> 5;
    int lane = t & 31;
    int g    = lane >> 2;            // groupID
    int tig  = lane & 3;             // thread-in-group
    int wm   = (wid & 1) * 32;
    int wn   = (wid >> 1) * 64;

    float d[2][8][4];
    #pragma unroll
    for (int mi = 0; mi < 2; mi++)
        #pragma unroll
        for (int ni = 0; ni < 8; ni++)
            #pragma unroll
            for (int r = 0; r < 4; r++) d[mi][ni][r] = 0.f;

    const float* inb = in + ((size_t)b * ictot + icoff) * HW + pbase;

    for (int k0 = 0; k0 < ic; k0 += 16) {
        #pragma unroll
        for (int l = 0; l < 16; l++)       // 16 x 256 input tile, tf32 rounded
            sIn[l * 264 + t] = tf32_rna(inb[(size_t)(k0 + l) * HW + t]);
        #pragma unroll
        for (int l = 0; l < 4; l++) {      // 16 x 64 weight tile (already tf32)
            int idx = l * 256 + t;
            int r = idx >> 6, cc = idx & 63;
            sW[r * 72 + cc] = Wt[(size_t)(k0 + r) * octot + ocbase + cc];
        }
        __syncthreads();
        #pragma unroll
        for (int k8 = 0; k8 < 2; k8++) {
            unsigned a[2][4];
            #pragma unroll
            for (int mi = 0; mi < 2; mi++) {
                int m = wm + mi * 16 + g;
                a[mi][0] = sW[(k8 * 8 + tig) * 72 + m];
                a[mi][1] = sW[(k8 * 8 + tig) * 72 + m + 8];
                a[mi][2] = sW[(k8 * 8 + tig + 4) * 72 + m];
                a[mi][3] = sW[(k8 * 8 + tig + 4) * 72 + m + 8];
            }
            #pragma unroll
            for (int ni = 0; ni < 8; ni++) {
                int px = wn + ni * 8 + g;
                unsigned b0 = sIn[(k8 * 8 + tig) * 264 + px];
                unsigned b1 = sIn[(k8 * 8 + tig + 4) * 264 + px];
                mma_tf32(d[0][ni], a[0], b0, b1);
                mma_tf32(d[1][ni], a[1], b0, b1);
            }
        }
        __syncthreads();
    }

    #pragma unroll
    for (int mi = 0; mi < 2; mi++) {
        #pragma unroll
        for (int ni = 0; ni < 8; ni++) {
            int oc0 = ocbase + wm + mi * 16 + g;
            int px  = pbase + wn + ni * 8 + tig * 2;
            size_t off0 = ((size_t)b * octot + oc0) * HW + px;
            size_t off1 = off0 + (size_t)8 * HW;
            float2 r0 = make_float2(d[mi][ni][0], d[mi][ni][1]);
            float2 r1 = make_float2(d[mi][ni][2], d[mi][ni][3]);
            if (res) {
                float2 e0 = *reinterpret_cast<const float2*>(res + off0);
                float2 e1 = *reinterpret_cast<const float2*>(res + off1);
                r0.x += e0.x; r0.y += e0.y; r1.x += e1.x; r1.y += e1.y;
            }
            *reinterpret_cast<float2*>(out + off0) = r0;
            *reinterpret_cast<float2*>(out + off1) = r1;
        }
    }
}

// ---------------- depthwise 3x3, zero pad ------------------------------------------
__global__ void dwconv_kernel(const float* __restrict__ in, const float* __restrict__ w,
                              int C, float* __restrict__ out) {
    size_t idx = (size_t)blockIdx.x * blockDim.x + threadIdx.x;
    size_t total = (size_t)2 * C * HW;
    if (idx >= total) return;
    int x = (int)(idx & 127);
    int y = (int)((idx >> 7) & 127);
    int c = (int)((idx >> 14) % C);
    const float* wp = w + c * 9;
    const float* ip = in + (idx - (idx & (HW - 1)));
    float acc = 0.f;
    #pragma unroll
    for (int ky = 0; ky < 3; ky++) {
        int yy = y + ky - 1;
        if (yy < 0 || yy > 127) continue;
        #pragma unroll
        for (int kx = 0; kx < 3; kx++) {
            int xx = x + kx - 1;
            if (xx < 0 || xx > 127) continue;
            acc += ip[yy * IMW + xx] * wp[ky * 3 + kx];
        }
    }
    out[idx] = acc;
}

// ---------------- reciprocal L2 norm over HW per (b, channel) row ------------------
__global__ void rnorm_kernel(const float* __restrict__ t, int chtot, int coff,
                             float* __restrict__ rn) {
    int row = blockIdx.x;
    int b = row / 192, c = row % 192;
    const float* p = t + ((size_t)b * chtot + coff + c) * HW;
    float s = 0.f;
    for (int i = threadIdx.x; i < HW; i += blockDim.x) { float v = p[i]; s += v * v; }
    __shared__ float red[8];
    #pragma unroll
    for (int o = 16; o; o >>= 1) s += __shfl_down_sync(0xffffffffu, s, o);
    if ((threadIdx.x & 31) == 0) red[threadIdx.x >> 5] = s;
    __syncthreads();
    if (threadIdx.x < 32) {
        s = (threadIdx.x < 8) ? red[threadIdx.x] : 0.f;
        #pragma unroll
        for (int o = 4; o; o >>= 1) s += __shfl_down_sync(0xffffffffu, s, o);
        if (threadIdx.x == 0) rn[row] = 1.0f / fmaxf(sqrtf(s), 1e-12f);
    }
}

// ---------------- q@k^T partials ----------------------------------------------------
__global__ void qk_kernel(const float* __restrict__ q, const float* __restrict__ kv,
                          float* __restrict__ Sp) {
    int pc = blockIdx.x, hh = blockIdx.y, b = blockIdx.z;
    const float* qb = q  + ((size_t)b * 192 + hh * 32) * HW + pc * 2048;
    const float* kb = kv + ((size_t)b * 384 + hh * 32) * HW + pc * 2048;
    __shared__ float sq[32 * 33];
    __shared__ float sk[32 * 33];
    int t = threadIdx.x;
    int i = t & 31, jg = t >> 5;
    float acc[4] = {0.f, 0.f, 0.f, 0.f};
    for (int p0 = 0; p0 < 2048; p0 += 32) {
        #pragma unroll
        for (int l = 0; l < 4; l++) {
            int idx = t + l * 256;
            int r = idx >> 5, cc = idx & 31;
            sq[r * 33 + cc] = qb[(size_t)r * HW + p0 + cc];
            sk[r * 33 + cc] = kb[(size_t)r * HW + p0 + cc];
        }
        __syncthreads();
        #pragma unroll
        for (int p = 0; p < 32; p++) {
            float a = sq[i * 33 + p];
            #pragma unroll
            for (int j = 0; j < 4; j++) acc[j] += a * sk[(jg * 4 + j) * 33 + p];
        }
        __syncthreads();
    }
    float* sp = Sp + (((size_t)(b * 6 + hh) * 8 + pc) * 1024);
    #pragma unroll
    for (int j = 0; j < 4; j++) sp[i * 32 + jg * 4 + j] = acc[j];
}

// ---------------- softmax over last dim ---------------------------------------------
__global__ void softmax_kernel(const float* __restrict__ Sp, const float* __restrict__ rq,
                               const float* __restrict__ rk, const float* __restrict__ temp,
                               float* __restrict__ attn) {
    int bh = blockIdx.x;
    int b = bh / 6, hh = bh % 6;
    int t = threadIdx.x;
    int i = t >> 5, j = t & 31;
    const float* sp = Sp + (size_t)bh * 8192 + i * 32 + j;
    float s = 0.f;
    #pragma unroll
    for (int pc = 0; pc < 8; pc++) s += sp[pc * 1024];
    s *= rq[b * 192 + hh * 32 + i] * rk[b * 192 + hh * 32 + j] * temp[hh];
    float mx = s;
    #pragma unroll
    for (int o = 16; o; o >>= 1) mx = fmaxf(mx, __shfl_xor_sync(0xffffffffu, mx, o));
    float e = expf(s - mx);
    float sum = e;
    #pragma unroll
    for (int o = 16; o; o >>= 1) sum += __shfl_xor_sync(0xffffffffu, sum, o);
    attn[(size_t)bh * 1024 + i * 32 + j] = e / sum;
}

// ---------------- out = attn @ v ----------------------------------------------------
__global__ void av_kernel(const float* __restrict__ attn, const float* __restrict__ kv,
                          float* __restrict__ out) {
    int b = blockIdx.z, hh = blockIdx.y;
    int p = blockIdx.x * 256 + threadIdx.x;
    __shared__ float sA[1024];
    for (int l = threadIdx.x; l < 1024; l += 256)
        sA[l] = attn[(size_t)(b * 6 + hh) * 1024 + l];
    __syncthreads();
    const float* vb = kv + ((size_t)b * 384 + 192 + hh * 32) * HW + p;
    float v[32];
    #pragma unroll
    for (int e = 0; e < 32; e++) v[e] = vb[(size_t)e * HW];
    float* ob = out + ((size_t)b * 192 + hh * 32) * HW + p;
    #pragma unroll
    for (int i = 0; i < 32; i++) {
        float acc = 0.f;
        #pragma unroll
        for (int e = 0; e < 32; e++) acc += sA[i * 32 + e] * v[e];
        ob[(size_t)i * HW] = acc;
    }
}

// ---------------- gelu(y1) * y2 -----------------------------------------------------
__global__ void gelu_gate_kernel(const float* __restrict__ y, float* __restrict__ g) {
    size_t idx = (size_t)blockIdx.x * blockDim.x + threadIdx.x;
    if (idx >= (size_t)2 * 384 * HW) return;
    size_t b = idx / ((size_t)384 * HW);
    size_t r = idx % ((size_t)384 * HW);
    const float* yb = y + b * 768 * HW;
    float a  = yb[r];
    float g2 = yb[r + (size_t)384 * HW];
    float ge = 0.5f * a * (1.0f + erff(a * 0.70710678118654752f));
    g[idx] = ge * g2;
}

// ====================================================================================
extern "C" void kernel_launch(void* const* d_in, const int* in_sizes, int n_in,
                              void* d_out, int out_size) {
    const float* x      = (const float*)d_in[0];
    const float* k_v    = (const float*)d_in[1];
    const float* ln1_w  = (const float*)d_in[2];
    const float* ln1_b  = (const float*)d_in[3];
    const float* temp   = (const float*)d_in[4];
    const float* w_kR   = (const float*)d_in[5];
    const float* w_kI   = (const float*)d_in[6];
    const float* w_qR   = (const float*)d_in[7];
    const float* w_qdw  = (const float*)d_in[8];
    const float* w_kvI  = (const float*)d_in[9];
    const float* w_kvdw = (const float*)d_in[10];
    const float* w_po   = (const float*)d_in[11];
    const float* ln2_w  = (const float*)d_in[12];
    const float* ln2_b  = (const float*)d_in[13];
    const float* w_ffk  = (const float*)d_in[14];
    const float* w_pin  = (const float*)d_in[15];
    const float* w_dw   = (const float*)d_in[16];
    const float* w_pout = (const float*)d_in[17];
    float* out = (float*)d_out;

    float* scratch = nullptr;
    cudaGetSymbolAddress((void**)&scratch, g_scratch);
    float* xs  = scratch + OFF_XS;
    float* t1  = scratch + OFF_T1;
    float* q   = scratch + OFF_Q;
    float* kvp = scratch + OFF_KVP;
    float* kvb = scratch + OFF_KV;
    float* yp  = scratch + OFF_YP;
    float* yb  = scratch + OFF_Y;
    float* m1  = scratch + OFF_M1;
    float* mf  = scratch + OFF_MF;
    float* rq  = scratch + OFF_RQ;
    float* rk  = scratch + OFF_RK;
    float* Sp  = scratch + OFF_SP;
    float* att = scratch + OFF_ATT;
    unsigned* wqr   = (unsigned*)(scratch + OFF_WQR);
    unsigned* wkvi  = (unsigned*)(scratch + OFF_WKVI);
    unsigned* wpo   = (unsigned*)(scratch + OFF_WPO);
    unsigned* wpin  = (unsigned*)(scratch + OFF_WPIN);
    unsigned* wpout = (unsigned*)(scratch + OFF_WPOUT);

    int tail = out_size - 6291456;
    if (tail < 0) tail = 0;
    if (tail > 512) tail = 512;

    // prep: channel multipliers + k_v passthrough + tf32 transposed weights
    prep_kernel<<<5, 256>>>(k_v, w_kR, w_kI, w_ffk, m1, mf, out + 6291456, tail);
    wprep_kernel<<<(192 * 144 + 255) / 256, 256>>>(w_qR, 192, 144, wqr);
    wprep_kernel<<<(384 * 48 + 255) / 256, 256>>>(w_kvI, 384, 48, wkvi);
    wprep_kernel<<<(192 * 192 + 255) / 256, 256>>>(w_po, 192, 192, wpo);
    wprep_kernel<<<(768 * 192 + 255) / 256, 256>>>(w_pin, 768, 192, wpin);
    wprep_kernel<<<(192 * 384 + 255) / 256, 256>>>(w_pout, 192, 384, wpout);

    // ---- attention branch ----
    ln_scale_kernel<<<128, 256>>>(x, ln1_w, ln1_b, m1, xs);
    conv1x1_tc_kernel<<<dim3(128, 3, 2), 256>>>(xs, 192, 0, 144, wqr, 192, nullptr, t1);
    conv1x1_tc_kernel<<<dim3(128, 6, 2), 256>>>(xs, 192, 144, 48, wkvi, 384, nullptr, kvp);
    dwconv_kernel<<<(2 * 192 * HW) / 256, 256>>>(t1, w_qdw, 192, q);
    dwconv_kernel<<<(2 * 384 * HW) / 256, 256>>>(kvp, w_kvdw, 384, kvb);
    rnorm_kernel<<<384, 256>>>(q, 192, 0, rq);
    rnorm_kernel<<<384, 256>>>(kvb, 384, 0, rk);
    qk_kernel<<<dim3(8, 6, 2), 256>>>(q, kvb, Sp);
    softmax_kernel<<<12, 1024>>>(Sp, rq, rk, temp, att);
    av_kernel<<<dim3(64, 6, 2), 256>>>(att, kvb, t1);
    conv1x1_tc_kernel<<<dim3(128, 3, 2), 256>>>(t1, 192, 0, 192, wpo, 192, x, out);

    // ---- GDFN feed-forward ----
    ln_scale_kernel<<<128, 256>>>(out, ln2_w, ln2_b, mf, xs);
    conv1x1_tc_kernel<<<dim3(128, 12, 2), 256>>>(xs, 192, 0, 192, wpin, 768, nullptr, yp);
    dwconv_kernel<<<(2 * 768 * HW) / 256, 256>>>(yp, w_dw, 768, yb);
    gelu_gate_kernel<<<(2 * 384 * HW) / 256, 256>>>(yb, kvp);
    conv1x1_tc_kernel<<<dim3(128, 3, 2), 256>>>(kvp, 384, 0, 384, wpout, 192, out, out);
}